// round 1
// baseline (speedup 1.0000x reference)
#include <cuda_runtime.h>
#include <math.h>

#define D 320
#define NCAT 20
#define NTYPE 10
#define NVAR 4
#define NSPAT 20
#define NTOK 32768
#define TYPE_BASE 20
#define VAR_BASE 220
#define SPAT_BASE 1020
#define NPROJ 1040

// Scratch (no allocs allowed): projected codes (pre-scaled by 1/tau), bias consts, per-token category.
__device__ float g_proj[NPROJ * D];
__device__ float g_const[NPROJ];
__device__ int   g_cat[NTOK];

// ---------------------------------------------------------------------------
// Precompute: proj_j = (c_j @ W) / tau, const_j = (b . c_j) / tau
// 10 codes per block, 320 threads (one output dim each). W streamed once/block.
// ---------------------------------------------------------------------------
__global__ __launch_bounds__(320) void proj_kernel(
    const float* __restrict__ catc, const float* __restrict__ typc,
    const float* __restrict__ varc, const float* __restrict__ spac,
    const float* __restrict__ Wc, const float* __restrict__ bc,
    const float* __restrict__ Wt, const float* __restrict__ bt,
    const float* __restrict__ Wv, const float* __restrict__ bv,
    const float* __restrict__ Ws, const float* __restrict__ bs,
    const float* __restrict__ log_tau)
{
    __shared__ float csm[10 * D];
    __shared__ float red[320];
    int j0 = blockIdx.x * 10;
    const float *W, *b, *src;
    if (j0 < TYPE_BASE)      { W = Wc; b = bc; src = catc + j0 * D; }
    else if (j0 < VAR_BASE)  { W = Wt; b = bt; src = typc + (j0 - TYPE_BASE) * D; }
    else if (j0 < SPAT_BASE) { W = Wv; b = bv; src = varc + (j0 - VAR_BASE) * D; }
    else                     { W = Ws; b = bs; src = spac + (j0 - SPAT_BASE) * D; }
    int k = threadIdx.x;
    for (int i = k; i < 10 * D; i += 320) csm[i] = src[i];
    __syncthreads();

    float tau = fminf(fmaxf(expf(log_tau[0]) + 0.1f, 0.1f), 2.0f);
    float it = 1.0f / tau;

    float acc[10];
    #pragma unroll
    for (int j = 0; j < 10; j++) acc[j] = 0.f;
    for (int d = 0; d < D; d++) {
        float w = W[d * D + k];   // coalesced column walk of W (row-major [out=k? no: W[k_out][d_in]])
        #pragma unroll
        for (int j = 0; j < 10; j++) acc[j] = fmaf(csm[j * D + d], w, acc[j]);
    }
    // NOTE orientation: q[k] = sum_d h[d]*W[k][d]; sim_j = sum_k q[k]*c_j[k]
    //   => proj_j[d] = sum_k c_j[k]*W[k][d]. Loop variable 'd' above iterates the k
    //   (row) index of W and 'k' (threadIdx) is the d (column) index. Correct as written:
    //   acc[j] = sum_row csm[j][row] * W[row*D + col] with col=threadIdx.
    #pragma unroll
    for (int j = 0; j < 10; j++) g_proj[(j0 + j) * D + k] = acc[j] * it;

    for (int j = 0; j < 10; j++) {
        red[k] = b[k] * csm[j * D + k];
        __syncthreads();
        if (k < 160) red[k] += red[k + 160]; __syncthreads();
        if (k < 80)  red[k] += red[k + 80];  __syncthreads();
        if (k < 40)  red[k] += red[k + 40];  __syncthreads();
        if (k < 20)  red[k] += red[k + 20];  __syncthreads();
        if (k < 10)  red[k] += red[k + 10];  __syncthreads();
        if (k < 5)   red[k] += red[k + 5];   __syncthreads();
        if (k == 0) g_const[j0 + j] = (red[0] + red[1] + red[2] + red[3] + red[4]) * it;
        __syncthreads();
    }
}

// ---------------------------------------------------------------------------
// Warp-per-token helpers. Lane l owns dim pairs {64*i + 2*l, 64*i + 2*l + 1}, i=0..4.
// ---------------------------------------------------------------------------
__device__ __forceinline__ float warp_dot(const float* __restrict__ row,
                                          const float2* h, int lane) {
    const float2* r = (const float2*)row;
    float a = 0.f;
    #pragma unroll
    for (int i = 0; i < 5; i++) {
        float2 v = r[i * 32 + lane];
        a = fmaf(h[i].x, v.x, a);
        a = fmaf(h[i].y, v.y, a);
    }
    #pragma unroll
    for (int o = 16; o > 0; o >>= 1) a += __shfl_xor_sync(0xffffffffu, a, o);
    return a;
}

__device__ __forceinline__ void acc_row(const float* __restrict__ row, float p,
                                        float2* z, int lane) {
    const float2* r = (const float2*)row;
    #pragma unroll
    for (int i = 0; i < 5; i++) {
        float2 v = r[i * 32 + lane];
        z[i].x = fmaf(p, v.x, z[i].x);
        z[i].y = fmaf(p, v.y, z[i].y);
    }
}

// ---------------------------------------------------------------------------
// Phase A: category + spatial. Persistent warps; cat/spatial codes (proj+orig) in smem.
// Writes out = z_c + z_s, and g_cat[t].
// ---------------------------------------------------------------------------
#define SMEM_A ((80 * D + 40) * 4)
__global__ __launch_bounds__(256) void phaseA_kernel(
    const float* __restrict__ x, const float* __restrict__ cat_codes,
    const float* __restrict__ spat_codes, float* __restrict__ out)
{
    extern __shared__ float sm[];
    float* sCp = sm;                 // 20*D  projected category
    float* sCo = sCp + 20 * D;       // 20*D  original category
    float* sSp = sCo + 20 * D;       // 20*D  projected spatial
    float* sSo = sSp + 20 * D;       // 20*D  original spatial
    float* sCc = sSo + 20 * D;       // 20 consts
    float* sSc = sCc + 20;           // 20 consts

    for (int i = threadIdx.x; i < 20 * D; i += blockDim.x) {
        sCp[i] = g_proj[i];
        sCo[i] = cat_codes[i];
        sSp[i] = g_proj[SPAT_BASE * D + i];
        sSo[i] = spat_codes[i];
    }
    if (threadIdx.x < 20) {
        sCc[threadIdx.x] = g_const[threadIdx.x];
        sSc[threadIdx.x] = g_const[SPAT_BASE + threadIdx.x];
    }
    __syncthreads();

    int lane = threadIdx.x & 31;
    int warp = threadIdx.x >> 5;
    int gw = blockIdx.x * (blockDim.x >> 5) + warp;
    int nwarps = gridDim.x * (blockDim.x >> 5);

    for (int t = gw; t < NTOK; t += nwarps) {
        float2 h[5];
        const float2* xp = (const float2*)(x + (size_t)t * D);
        #pragma unroll
        for (int i = 0; i < 5; i++) h[i] = xp[i * 32 + lane];

        float2 z[5];
        #pragma unroll
        for (int i = 0; i < 5; i++) { z[i].x = 0.f; z[i].y = 0.f; }

        // --- category ---
        float sim[20];
        #pragma unroll
        for (int j = 0; j < 20; j++) sim[j] = warp_dot(sCp + j * D, h, lane) + sCc[j];
        float m = sim[0]; int ci = 0;
        #pragma unroll
        for (int j = 1; j < 20; j++) if (sim[j] > m) { m = sim[j]; ci = j; }
        float s = 0.f;
        #pragma unroll
        for (int j = 0; j < 20; j++) { sim[j] = __expf(sim[j] - m); s += sim[j]; }
        float inv = 1.f / s;
        #pragma unroll
        for (int j = 0; j < 20; j++) acc_row(sCo + j * D, sim[j] * inv, z, lane);
        if (lane == 0) g_cat[t] = ci;

        // --- spatial ---
        #pragma unroll
        for (int j = 0; j < 20; j++) sim[j] = warp_dot(sSp + j * D, h, lane) + sSc[j];
        m = sim[0];
        #pragma unroll
        for (int j = 1; j < 20; j++) m = fmaxf(m, sim[j]);
        s = 0.f;
        #pragma unroll
        for (int j = 0; j < 20; j++) { sim[j] = __expf(sim[j] - m); s += sim[j]; }
        inv = 1.f / s;
        #pragma unroll
        for (int j = 0; j < 20; j++) acc_row(sSo + j * D, sim[j] * inv, z, lane);

        float2* op = (float2*)(out + (size_t)t * D);
        #pragma unroll
        for (int i = 0; i < 5; i++) op[i * 32 + lane] = z[i];
    }
}

// ---------------------------------------------------------------------------
// Phase B: type + variant. 7 blocks per category; each block holds its category's
// 10 type rows + 40 variant rows (proj+orig, 128 KB) in smem. Warps ballot-scan
// g_cat to self-select their tokens. out[t] += z_t + z_v.
// ---------------------------------------------------------------------------
#define NB_PER_CAT 7
#define TPB_B 512
#define SMEM_B ((100 * D + 50) * 4)
__global__ __launch_bounds__(TPB_B) void phaseB_kernel(
    const float* __restrict__ x, const float* __restrict__ type_codes,
    const float* __restrict__ var_codes, float* __restrict__ out)
{
    extern __shared__ float sm[];
    float* sTp = sm;                 // 10*D
    float* sTo = sTp + 10 * D;       // 10*D
    float* sVp = sTo + 10 * D;       // 40*D
    float* sVo = sVp + 40 * D;       // 40*D
    float* sTc = sVo + 40 * D;       // 10
    float* sVc = sTc + 10;           // 40

    int c = blockIdx.x / NB_PER_CAT;
    int b = blockIdx.x % NB_PER_CAT;

    for (int i = threadIdx.x; i < 10 * D; i += blockDim.x) {
        sTp[i] = g_proj[(TYPE_BASE + c * 10) * D + i];
        sTo[i] = type_codes[(size_t)c * 10 * D + i];
    }
    for (int i = threadIdx.x; i < 40 * D; i += blockDim.x) {
        sVp[i] = g_proj[(VAR_BASE + c * 40) * D + i];
        sVo[i] = var_codes[(size_t)c * 40 * D + i];
    }
    if (threadIdx.x < 10) sTc[threadIdx.x] = g_const[TYPE_BASE + c * 10 + threadIdx.x];
    if (threadIdx.x < 40) sVc[threadIdx.x] = g_const[VAR_BASE + c * 40 + threadIdx.x];
    __syncthreads();

    int lane = threadIdx.x & 31;
    int warp = threadIdx.x >> 5;
    const int NW = NB_PER_CAT * (TPB_B / 32);         // 112 warps per category
    int gw = b * (TPB_B / 32) + warp;                 // 0..111
    int chunk = (NTOK + NW - 1) / NW;                 // 293
    int t0 = gw * chunk;
    int t1 = min(t0 + chunk, NTOK);

    for (int tb = t0; tb < t1; tb += 32) {
        int t = tb + lane;
        int myc = (t < t1) ? g_cat[t] : -1;
        unsigned mask = __ballot_sync(0xffffffffu, myc == c);
        while (mask) {
            int bit = __ffs(mask) - 1;
            mask &= mask - 1;
            int tok = tb + bit;

            float2 h[5];
            const float2* xp = (const float2*)(x + (size_t)tok * D);
            #pragma unroll
            for (int i = 0; i < 5; i++) h[i] = xp[i * 32 + lane];

            // --- type (only this category's 10 rows are unmasked) ---
            float simT[10];
            #pragma unroll
            for (int k = 0; k < 10; k++) simT[k] = warp_dot(sTp + k * D, h, lane) + sTc[k];
            float m = simT[0]; int lt = 0;
            #pragma unroll
            for (int k = 1; k < 10; k++) if (simT[k] > m) { m = simT[k]; lt = k; }
            float s = 0.f;
            #pragma unroll
            for (int k = 0; k < 10; k++) { simT[k] = __expf(simT[k] - m); s += simT[k]; }
            float inv = 1.f / s;

            float2 z[5];
            #pragma unroll
            for (int i = 0; i < 5; i++) { z[i].x = 0.f; z[i].y = 0.f; }
            #pragma unroll
            for (int k = 0; k < 10; k++) acc_row(sTo + k * D, simT[k] * inv, z, lane);

            // --- variant (4 rows of selected type) ---
            int vb = lt * 4;
            float simV[4];
            #pragma unroll
            for (int v = 0; v < 4; v++) simV[v] = warp_dot(sVp + (vb + v) * D, h, lane) + sVc[vb + v];
            float mv = fmaxf(fmaxf(simV[0], simV[1]), fmaxf(simV[2], simV[3]));
            float sv = 0.f;
            #pragma unroll
            for (int v = 0; v < 4; v++) { simV[v] = __expf(simV[v] - mv); sv += simV[v]; }
            float invv = 1.f / sv;
            #pragma unroll
            for (int v = 0; v < 4; v++) acc_row(sVo + (vb + v) * D, simV[v] * invv, z, lane);

            float2* op = (float2*)(out + (size_t)tok * D);
            #pragma unroll
            for (int i = 0; i < 5; i++) {
                float2 o = op[i * 32 + lane];
                o.x += z[i].x; o.y += z[i].y;
                op[i * 32 + lane] = o;
            }
        }
    }
}

// ---------------------------------------------------------------------------
extern "C" void kernel_launch(void* const* d_in, const int* in_sizes, int n_in,
                              void* d_out, int out_size) {
    const float* x    = (const float*)d_in[0];
    const float* catc = (const float*)d_in[1];
    const float* typc = (const float*)d_in[2];
    const float* varc = (const float*)d_in[3];
    const float* spac = (const float*)d_in[4];
    const float* ltau = (const float*)d_in[5];
    const float* Wc   = (const float*)d_in[6];
    const float* bc   = (const float*)d_in[7];
    const float* Wt   = (const float*)d_in[8];
    const float* bt   = (const float*)d_in[9];
    const float* Wv   = (const float*)d_in[10];
    const float* bv   = (const float*)d_in[11];
    const float* Ws   = (const float*)d_in[12];
    const float* bs   = (const float*)d_in[13];
    float* out = (float*)d_out;

    cudaFuncSetAttribute(phaseA_kernel, cudaFuncAttributeMaxDynamicSharedMemorySize, SMEM_A);
    cudaFuncSetAttribute(phaseB_kernel, cudaFuncAttributeMaxDynamicSharedMemorySize, SMEM_B);

    proj_kernel<<<NPROJ / 10, 320>>>(catc, typc, varc, spac,
                                     Wc, bc, Wt, bt, Wv, bv, Ws, bs, ltau);
    phaseA_kernel<<<296, 256, SMEM_A>>>(x, catc, spac, out);
    phaseB_kernel<<<NCAT * NB_PER_CAT, TPB_B, SMEM_B>>>(x, typc, varc, out);
}

// round 4
// speedup vs baseline: 1.2044x; 1.2044x over previous
#include <cuda_runtime.h>
#include <math.h>

#define D 320
#define NCAT 20
#define NTOK 32768
#define TYPE_BASE 20
#define VAR_BASE 220
#define SPAT_BASE 1020
#define NPROJ 1040
#define ROWB 1280           // bytes per code row (320 f32)

typedef unsigned long long u64;

// Scratch (no allocs allowed)
__device__ float g_proj[NPROJ * D];   // projected codes, pre-scaled by 1/tau
__device__ float g_const[NPROJ];      // (b . c_j)/tau
__device__ int   g_cat[NTOK];

// ---------------------------------------------------------------------------
// f32x2 / shared-mem primitives
// ---------------------------------------------------------------------------
__device__ __forceinline__ void fma2(u64& d, u64 a, u64 b) {
    asm("fma.rn.f32x2 %0, %1, %2, %0;" : "+l"(d) : "l"(a), "l"(b));
}
__device__ __forceinline__ u64 add2(u64 a, u64 b) {
    u64 d; asm("add.rn.f32x2 %0, %1, %2;" : "=l"(d) : "l"(a), "l"(b)); return d;
}
__device__ __forceinline__ float2 un2(u64 v) {
    float2 f; asm("mov.b64 {%0, %1}, %2;" : "=f"(f.x), "=f"(f.y) : "l"(v)); return f;
}
__device__ __forceinline__ u64 pk2(float x, float y) {
    u64 v; asm("mov.b64 %0, {%1, %2};" : "=l"(v) : "f"(x), "f"(y)); return v;
}
__device__ __forceinline__ void lds128(u64& a, u64& b, unsigned addr) {
    asm volatile("ld.shared.v2.u64 {%0, %1}, [%2];" : "=l"(a), "=l"(b) : "r"(addr));
}
__device__ __forceinline__ u64 lds64(unsigned addr) {
    u64 a; asm volatile("ld.shared.u64 %0, [%1];" : "=l"(a) : "r"(addr)); return a;
}
__device__ __forceinline__ unsigned s2u(const void* p) {
    return (unsigned)__cvta_generic_to_shared(p);
}
// Paired warp reduction: reduces a and b simultaneously via f32x2 butterfly.
__device__ __forceinline__ float2 wsum2(float a, float b) {
    u64 v = pk2(a, b);
    #pragma unroll
    for (int o = 16; o > 0; o >>= 1)
        v = add2(v, __shfl_xor_sync(0xffffffffu, v, o));
    return un2(v);
}
__device__ __forceinline__ float wsum1(float a) {
    #pragma unroll
    for (int o = 16; o > 0; o >>= 1)
        a += __shfl_xor_sync(0xffffffffu, a, o);
    return a;
}

// Lane l owns: pairs {2l,2l+1} (bytes 16l), {64+2l,...} (512+16l), {128+l} (1024+8l)
__device__ __forceinline__ void load_h(const float* xrow, u64 h[5], int lane) {
    const ulonglong2* p2 = (const ulonglong2*)xrow;
    ulonglong2 v0 = p2[lane];
    ulonglong2 v1 = p2[32 + lane];
    h[0] = v0.x; h[1] = v0.y; h[2] = v1.x; h[3] = v1.y;
    h[4] = ((const u64*)xrow)[128 + lane];
}

__device__ __forceinline__ void dot2(unsigned r, const u64* hA, const u64* hB,
                                     float& sA, float& sB, int lane) {
    u64 a0, a1, b0, b1, c;
    lds128(a0, a1, r + 16 * lane);
    lds128(b0, b1, r + 512 + 16 * lane);
    c = lds64(r + 1024 + 8 * lane);
    u64 xA = 0ull, xB = 0ull;
    fma2(xA, hA[0], a0); fma2(xA, hA[1], a1); fma2(xA, hA[2], b0); fma2(xA, hA[3], b1); fma2(xA, hA[4], c);
    fma2(xB, hB[0], a0); fma2(xB, hB[1], a1); fma2(xB, hB[2], b0); fma2(xB, hB[3], b1); fma2(xB, hB[4], c);
    float2 fA = un2(xA), fB = un2(xB);
    float2 r2 = wsum2(fA.x + fA.y, fB.x + fB.y);
    sA = r2.x; sB = r2.y;
}

__device__ __forceinline__ float dot1(unsigned r, const u64* h, int lane) {
    u64 a0, a1, b0, b1, c;
    lds128(a0, a1, r + 16 * lane);
    lds128(b0, b1, r + 512 + 16 * lane);
    c = lds64(r + 1024 + 8 * lane);
    u64 x = 0ull;
    fma2(x, h[0], a0); fma2(x, h[1], a1); fma2(x, h[2], b0); fma2(x, h[3], b1); fma2(x, h[4], c);
    float2 f = un2(x);
    return wsum1(f.x + f.y);
}

__device__ __forceinline__ void acc2(unsigned r, u64 pA, u64 pB, u64* zA, u64* zB, int lane) {
    u64 a0, a1, b0, b1, c;
    lds128(a0, a1, r + 16 * lane);
    lds128(b0, b1, r + 512 + 16 * lane);
    c = lds64(r + 1024 + 8 * lane);
    fma2(zA[0], pA, a0); fma2(zA[1], pA, a1); fma2(zA[2], pA, b0); fma2(zA[3], pA, b1); fma2(zA[4], pA, c);
    fma2(zB[0], pB, a0); fma2(zB[1], pB, a1); fma2(zB[2], pB, b0); fma2(zB[3], pB, b1); fma2(zB[4], pB, c);
}

__device__ __forceinline__ void acc1(unsigned r, u64 p, u64* z, int lane) {
    u64 a0, a1, b0, b1, c;
    lds128(a0, a1, r + 16 * lane);
    lds128(b0, b1, r + 512 + 16 * lane);
    c = lds64(r + 1024 + 8 * lane);
    fma2(z[0], p, a0); fma2(z[1], p, a1); fma2(z[2], p, b0); fma2(z[3], p, b1); fma2(z[4], p, c);
}

// ---------------------------------------------------------------------------
// Precompute: proj_j = (c_j @ W)/tau, const_j = (b.c_j)/tau. 10 codes/block.
// MLP=8 on W loads, f32x2 on the reduction dim.
// ---------------------------------------------------------------------------
__global__ __launch_bounds__(320) void proj_kernel(
    const float* __restrict__ catc, const float* __restrict__ typc,
    const float* __restrict__ varc, const float* __restrict__ spac,
    const float* __restrict__ Wc, const float* __restrict__ bc,
    const float* __restrict__ Wt, const float* __restrict__ bt,
    const float* __restrict__ Wv, const float* __restrict__ bv,
    const float* __restrict__ Ws, const float* __restrict__ bs,
    const float* __restrict__ log_tau)
{
    __shared__ float csm[10 * D];
    __shared__ float red[320];
    int j0 = blockIdx.x * 10;
    const float *W, *b, *src;
    if (j0 < TYPE_BASE)      { W = Wc; b = bc; src = catc + j0 * D; }
    else if (j0 < VAR_BASE)  { W = Wt; b = bt; src = typc + (j0 - TYPE_BASE) * D; }
    else if (j0 < SPAT_BASE) { W = Wv; b = bv; src = varc + (j0 - VAR_BASE) * D; }
    else                     { W = Ws; b = bs; src = spac + (j0 - SPAT_BASE) * D; }
    int k = threadIdx.x;
    for (int i = k; i < 10 * D; i += 320) csm[i] = src[i];
    __syncthreads();

    float tau = fminf(fmaxf(expf(log_tau[0]) + 0.1f, 0.1f), 2.0f);
    float it = 1.0f / tau;

    unsigned cbase = s2u(csm);
    u64 acc[10];
    #pragma unroll
    for (int j = 0; j < 10; j++) acc[j] = 0ull;

    for (int d0 = 0; d0 < D; d0 += 8) {
        float w[8];
        #pragma unroll
        for (int u = 0; u < 8; u++) w[u] = W[(d0 + u) * D + k];
        #pragma unroll
        for (int u = 0; u < 8; u += 2) {
            u64 wp = pk2(w[u], w[u + 1]);
            #pragma unroll
            for (int j = 0; j < 10; j++) {
                u64 cv = lds64(cbase + (j * D + d0 + u) * 4);
                fma2(acc[j], cv, wp);
            }
        }
    }
    #pragma unroll
    for (int j = 0; j < 10; j++) {
        float2 f = un2(acc[j]);
        g_proj[(j0 + j) * D + k] = (f.x + f.y) * it;
    }

    for (int j = 0; j < 10; j++) {
        red[k] = b[k] * csm[j * D + k];
        __syncthreads();
        if (k < 160) red[k] += red[k + 160]; __syncthreads();
        if (k < 80)  red[k] += red[k + 80];  __syncthreads();
        if (k < 40)  red[k] += red[k + 40];  __syncthreads();
        if (k < 20)  red[k] += red[k + 20];  __syncthreads();
        if (k < 10)  red[k] += red[k + 10];  __syncthreads();
        if (k < 5)   red[k] += red[k + 5];   __syncthreads();
        if (k == 0) g_const[j0 + j] = (red[0] + red[1] + red[2] + red[3] + red[4]) * it;
        __syncthreads();
    }
}

// ---------------------------------------------------------------------------
// Phase A: category + spatial. 2 tokens per warp iteration.
// ---------------------------------------------------------------------------
#define TPB_A 384
#define SMEM_A ((80 * D + 40) * 4)
__global__ __launch_bounds__(TPB_A, 1) void phaseA_kernel(
    const float* __restrict__ x, const float* __restrict__ cat_codes,
    const float* __restrict__ spat_codes, float* __restrict__ out)
{
    extern __shared__ float sm[];
    // [0) sCp, [20*D) sCo, [40*D) sSp, [60*D) sSo, [80*D) 40 consts
    for (int i = threadIdx.x; i < 20 * D; i += TPB_A) {
        sm[i]           = g_proj[i];
        sm[20 * D + i]  = cat_codes[i];
        sm[40 * D + i]  = g_proj[SPAT_BASE * D + i];
        sm[60 * D + i]  = spat_codes[i];
    }
    if (threadIdx.x < 20) {
        sm[80 * D + threadIdx.x]      = g_const[threadIdx.x];
        sm[80 * D + 20 + threadIdx.x] = g_const[SPAT_BASE + threadIdx.x];
    }
    __syncthreads();

    unsigned sb = s2u(sm);
    unsigned aCp = sb, aCo = sb + 20 * ROWB, aSp = sb + 40 * ROWB, aSo = sb + 60 * ROWB;
    const float* cc = sm + 80 * D;

    int lane = threadIdx.x & 31;
    int warp = threadIdx.x >> 5;
    int gw = blockIdx.x * (TPB_A / 32) + warp;
    int nw = gridDim.x * (TPB_A / 32);

    for (int p = gw; p < NTOK / 2; p += nw) {
        int tA = 2 * p, tB = 2 * p + 1;
        u64 hA[5], hB[5];
        load_h(x + (size_t)tA * D, hA, lane);
        load_h(x + (size_t)tB * D, hB, lane);
        u64 zA[5] = {0,0,0,0,0}, zB[5] = {0,0,0,0,0};
        float simA[20], simB[20];

        // --- category ---
        #pragma unroll
        for (int j = 0; j < 20; j++) {
            dot2(aCp + j * ROWB, hA, hB, simA[j], simB[j], lane);
            simA[j] += cc[j]; simB[j] += cc[j];
        }
        float mA = simA[0]; int ciA = 0;
        float mB = simB[0]; int ciB = 0;
        #pragma unroll
        for (int j = 1; j < 20; j++) {
            if (simA[j] > mA) { mA = simA[j]; ciA = j; }
            if (simB[j] > mB) { mB = simB[j]; ciB = j; }
        }
        float sA = 0.f, sB = 0.f;
        #pragma unroll
        for (int j = 0; j < 20; j++) {
            simA[j] = __expf(simA[j] - mA); sA += simA[j];
            simB[j] = __expf(simB[j] - mB); sB += simB[j];
        }
        float iA = 1.f / sA, iB = 1.f / sB;
        #pragma unroll
        for (int j = 0; j < 20; j++) {
            float pA = simA[j] * iA, pB = simB[j] * iB;
            acc2(aCo + j * ROWB, pk2(pA, pA), pk2(pB, pB), zA, zB, lane);
        }
        if (lane == 0) { g_cat[tA] = ciA; g_cat[tB] = ciB; }

        // --- spatial ---
        #pragma unroll
        for (int j = 0; j < 20; j++) {
            dot2(aSp + j * ROWB, hA, hB, simA[j], simB[j], lane);
            simA[j] += cc[20 + j]; simB[j] += cc[20 + j];
        }
        mA = simA[0]; mB = simB[0];
        #pragma unroll
        for (int j = 1; j < 20; j++) { mA = fmaxf(mA, simA[j]); mB = fmaxf(mB, simB[j]); }
        sA = 0.f; sB = 0.f;
        #pragma unroll
        for (int j = 0; j < 20; j++) {
            simA[j] = __expf(simA[j] - mA); sA += simA[j];
            simB[j] = __expf(simB[j] - mB); sB += simB[j];
        }
        iA = 1.f / sA; iB = 1.f / sB;
        #pragma unroll
        for (int j = 0; j < 20; j++) {
            float pA = simA[j] * iA, pB = simB[j] * iB;
            acc2(aSo + j * ROWB, pk2(pA, pA), pk2(pB, pB), zA, zB, lane);
        }

        float* oA = out + (size_t)tA * D;
        float* oB = out + (size_t)tB * D;
        ulonglong2 v;
        v.x = zA[0]; v.y = zA[1]; ((ulonglong2*)oA)[lane] = v;
        v.x = zA[2]; v.y = zA[3]; ((ulonglong2*)oA)[32 + lane] = v;
        ((u64*)oA)[128 + lane] = zA[4];
        v.x = zB[0]; v.y = zB[1]; ((ulonglong2*)oB)[lane] = v;
        v.x = zB[2]; v.y = zB[3]; ((ulonglong2*)oB)[32 + lane] = v;
        ((u64*)oB)[128 + lane] = zB[4];
    }
}

// ---------------------------------------------------------------------------
// Phase B: type + variant. 7 blocks/category; tokens paired via carried pend.
// ---------------------------------------------------------------------------
#define NB_PER_CAT 7
#define TPB_B 384
#define SMEM_B ((100 * D + 50) * 4)

__device__ __forceinline__ void processB(
    int tA, int tB, const float* __restrict__ x, float* __restrict__ out,
    unsigned aTp, unsigned aTo, unsigned aVp, unsigned aVo,
    const float* tc, const float* vc, int lane)
{
    u64 hA[5], hB[5];
    load_h(x + (size_t)tA * D, hA, lane);
    load_h(x + (size_t)tB * D, hB, lane);
    u64 zA[5] = {0,0,0,0,0}, zB[5] = {0,0,0,0,0};

    float simA[10], simB[10];
    #pragma unroll
    for (int k = 0; k < 10; k++) {
        dot2(aTp + k * ROWB, hA, hB, simA[k], simB[k], lane);
        simA[k] += tc[k]; simB[k] += tc[k];
    }
    float mA = simA[0]; int ltA = 0;
    float mB = simB[0]; int ltB = 0;
    #pragma unroll
    for (int k = 1; k < 10; k++) {
        if (simA[k] > mA) { mA = simA[k]; ltA = k; }
        if (simB[k] > mB) { mB = simB[k]; ltB = k; }
    }
    float sA = 0.f, sB = 0.f;
    #pragma unroll
    for (int k = 0; k < 10; k++) {
        simA[k] = __expf(simA[k] - mA); sA += simA[k];
        simB[k] = __expf(simB[k] - mB); sB += simB[k];
    }
    float iA = 1.f / sA, iB = 1.f / sB;
    #pragma unroll
    for (int k = 0; k < 10; k++) {
        float pA = simA[k] * iA, pB = simB[k] * iB;
        acc2(aTo + k * ROWB, pk2(pA, pA), pk2(pB, pB), zA, zB, lane);
    }

    // variant: selected-type rows differ per token
    {
        int vb = ltA * 4;
        float sv[4];
        #pragma unroll
        for (int v = 0; v < 4; v++) sv[v] = dot1(aVp + (vb + v) * ROWB, hA, lane) + vc[vb + v];
        float mv = fmaxf(fmaxf(sv[0], sv[1]), fmaxf(sv[2], sv[3]));
        float s = 0.f;
        #pragma unroll
        for (int v = 0; v < 4; v++) { sv[v] = __expf(sv[v] - mv); s += sv[v]; }
        float inv = 1.f / s;
        #pragma unroll
        for (int v = 0; v < 4; v++) { float pp = sv[v] * inv; acc1(aVo + (vb + v) * ROWB, pk2(pp, pp), zA, lane); }
    }
    {
        int vb = ltB * 4;
        float sv[4];
        #pragma unroll
        for (int v = 0; v < 4; v++) sv[v] = dot1(aVp + (vb + v) * ROWB, hB, lane) + vc[vb + v];
        float mv = fmaxf(fmaxf(sv[0], sv[1]), fmaxf(sv[2], sv[3]));
        float s = 0.f;
        #pragma unroll
        for (int v = 0; v < 4; v++) { sv[v] = __expf(sv[v] - mv); s += sv[v]; }
        float inv = 1.f / s;
        #pragma unroll
        for (int v = 0; v < 4; v++) { float pp = sv[v] * inv; acc1(aVo + (vb + v) * ROWB, pk2(pp, pp), zB, lane); }
    }

    // out += z (RMW)
    {
        float* o = out + (size_t)tA * D;
        ulonglong2* o2 = (ulonglong2*)o;
        ulonglong2 v = o2[lane];
        v.x = add2(v.x, zA[0]); v.y = add2(v.y, zA[1]); o2[lane] = v;
        v = o2[32 + lane];
        v.x = add2(v.x, zA[2]); v.y = add2(v.y, zA[3]); o2[32 + lane] = v;
        ((u64*)o)[128 + lane] = add2(((u64*)o)[128 + lane], zA[4]);
    }
    if (tB != tA) {
        float* o = out + (size_t)tB * D;
        ulonglong2* o2 = (ulonglong2*)o;
        ulonglong2 v = o2[lane];
        v.x = add2(v.x, zB[0]); v.y = add2(v.y, zB[1]); o2[lane] = v;
        v = o2[32 + lane];
        v.x = add2(v.x, zB[2]); v.y = add2(v.y, zB[3]); o2[32 + lane] = v;
        ((u64*)o)[128 + lane] = add2(((u64*)o)[128 + lane], zB[4]);
    }
}

__global__ __launch_bounds__(TPB_B, 1) void phaseB_kernel(
    const float* __restrict__ x, const float* __restrict__ type_codes,
    const float* __restrict__ var_codes, float* __restrict__ out)
{
    extern __shared__ float sm[];
    // [0) sTp(10), [10*D) sTo(10), [20*D) sVp(40), [60*D) sVo(40), [100*D) 50 consts
    int c = blockIdx.x / NB_PER_CAT;
    int b = blockIdx.x % NB_PER_CAT;

    for (int i = threadIdx.x; i < 10 * D; i += TPB_B) {
        sm[i]          = g_proj[(TYPE_BASE + c * 10) * D + i];
        sm[10 * D + i] = type_codes[(size_t)c * 10 * D + i];
    }
    for (int i = threadIdx.x; i < 40 * D; i += TPB_B) {
        sm[20 * D + i] = g_proj[(VAR_BASE + c * 40) * D + i];
        sm[60 * D + i] = var_codes[(size_t)c * 40 * D + i];
    }
    if (threadIdx.x < 10) sm[100 * D + threadIdx.x] = g_const[TYPE_BASE + c * 10 + threadIdx.x];
    if (threadIdx.x < 40) sm[100 * D + 10 + threadIdx.x] = g_const[VAR_BASE + c * 40 + threadIdx.x];
    __syncthreads();

    unsigned sb = s2u(sm);
    unsigned aTp = sb, aTo = sb + 10 * ROWB, aVp = sb + 20 * ROWB, aVo = sb + 60 * ROWB;
    const float* tc = sm + 100 * D;
    const float* vc = sm + 100 * D + 10;

    int lane = threadIdx.x & 31;
    int warp = threadIdx.x >> 5;
    const int NW = NB_PER_CAT * (TPB_B / 32);            // 84 warps per category
    int gwc = b * (TPB_B / 32) + warp;
    int chunk = (((NTOK + NW - 1) / NW) + 31) & ~31;     // 32-aligned
    int t0 = gwc * chunk;
    int t1 = min(t0 + chunk, NTOK);

    int pend = -1;
    for (int tb = t0; tb < t1; tb += 32) {
        int t = tb + lane;
        int myc = (t < t1) ? g_cat[t] : -1;
        unsigned mask = __ballot_sync(0xffffffffu, myc == c);
        while (mask) {
            int bit = __ffs(mask) - 1;
            mask &= mask - 1;
            int tok = tb + bit;
            if (pend < 0) pend = tok;
            else {
                processB(pend, tok, x, out, aTp, aTo, aVp, aVo, tc, vc, lane);
                pend = -1;
            }
        }
    }
    if (pend >= 0)
        processB(pend, pend, x, out, aTp, aTo, aVp, aVo, tc, vc, lane);
}

// ---------------------------------------------------------------------------
extern "C" void kernel_launch(void* const* d_in, const int* in_sizes, int n_in,
                              void* d_out, int out_size) {
    const float* x    = (const float*)d_in[0];
    const float* catc = (const float*)d_in[1];
    const float* typc = (const float*)d_in[2];
    const float* varc = (const float*)d_in[3];
    const float* spac = (const float*)d_in[4];
    const float* ltau = (const float*)d_in[5];
    const float* Wc   = (const float*)d_in[6];
    const float* bc   = (const float*)d_in[7];
    const float* Wt   = (const float*)d_in[8];
    const float* bt   = (const float*)d_in[9];
    const float* Wv   = (const float*)d_in[10];
    const float* bv   = (const float*)d_in[11];
    const float* Ws   = (const float*)d_in[12];
    const float* bs   = (const float*)d_in[13];
    float* out = (float*)d_out;

    cudaFuncSetAttribute(phaseA_kernel, cudaFuncAttributeMaxDynamicSharedMemorySize, SMEM_A);
    cudaFuncSetAttribute(phaseB_kernel, cudaFuncAttributeMaxDynamicSharedMemorySize, SMEM_B);

    proj_kernel<<<NPROJ / 10, 320>>>(catc, typc, varc, spac,
                                     Wc, bc, Wt, bt, Wv, bv, Ws, bs, ltau);
    phaseA_kernel<<<148, TPB_A, SMEM_A>>>(x, catc, spac, out);
    phaseB_kernel<<<NCAT * NB_PER_CAT, TPB_B, SMEM_B>>>(x, typc, varc, out);
}

// round 5
// speedup vs baseline: 1.3170x; 1.0935x over previous
#include <cuda_runtime.h>
#include <math.h>

#define D 320
#define NCAT 20
#define NTOK 32768
#define TYPE_BASE 20
#define VAR_BASE 220
#define SPAT_BASE 1020
#define NPROJ 1040
#define ROWB 1280           // bytes per code row (320 f32)

typedef unsigned long long u64;

// Scratch (no allocs allowed)
__device__ float g_proj[NPROJ * D];   // projected codes, pre-scaled by 1/tau
__device__ float g_const[NPROJ];      // (b . c_j)/tau
__device__ int   g_cat[NTOK];

// ---------------------------------------------------------------------------
// f32x2 / shared-mem primitives
// ---------------------------------------------------------------------------
__device__ __forceinline__ void fma2(u64& d, u64 a, u64 b) {
    asm("fma.rn.f32x2 %0, %1, %2, %0;" : "+l"(d) : "l"(a), "l"(b));
}
__device__ __forceinline__ u64 add2(u64 a, u64 b) {
    u64 d; asm("add.rn.f32x2 %0, %1, %2;" : "=l"(d) : "l"(a), "l"(b)); return d;
}
__device__ __forceinline__ float2 un2(u64 v) {
    float2 f; asm("mov.b64 {%0, %1}, %2;" : "=f"(f.x), "=f"(f.y) : "l"(v)); return f;
}
__device__ __forceinline__ u64 pk2(float x, float y) {
    u64 v; asm("mov.b64 %0, {%1, %2};" : "=l"(v) : "f"(x), "f"(y)); return v;
}
__device__ __forceinline__ void lds128(u64& a, u64& b, unsigned addr) {
    asm volatile("ld.shared.v2.u64 {%0, %1}, [%2];" : "=l"(a), "=l"(b) : "r"(addr));
}
__device__ __forceinline__ u64 lds64(unsigned addr) {
    u64 a; asm volatile("ld.shared.u64 %0, [%1];" : "=l"(a) : "r"(addr)); return a;
}
__device__ __forceinline__ unsigned s2u(const void* p) {
    return (unsigned)__cvta_generic_to_shared(p);
}
// Paired warp reduction: reduces a and b simultaneously via f32x2 butterfly.
__device__ __forceinline__ float2 wsum2(float a, float b) {
    u64 v = pk2(a, b);
    #pragma unroll
    for (int o = 16; o > 0; o >>= 1)
        v = add2(v, __shfl_xor_sync(0xffffffffu, v, o));
    return un2(v);
}
__device__ __forceinline__ float wsum1(float a) {
    #pragma unroll
    for (int o = 16; o > 0; o >>= 1)
        a += __shfl_xor_sync(0xffffffffu, a, o);
    return a;
}

// Lane l owns: pairs {2l,2l+1} (bytes 16l), {64+2l,...} (512+16l), {128+l} (1024+8l)
__device__ __forceinline__ void load_h(const float* xrow, u64 h[5], int lane) {
    const ulonglong2* p2 = (const ulonglong2*)xrow;
    ulonglong2 v0 = p2[lane];
    ulonglong2 v1 = p2[32 + lane];
    h[0] = v0.x; h[1] = v0.y; h[2] = v1.x; h[3] = v1.y;
    h[4] = ((const u64*)xrow)[128 + lane];
}

__device__ __forceinline__ void dot2(unsigned r, const u64* hA, const u64* hB,
                                     float& sA, float& sB, int lane) {
    u64 a0, a1, b0, b1, c;
    lds128(a0, a1, r + 16 * lane);
    lds128(b0, b1, r + 512 + 16 * lane);
    c = lds64(r + 1024 + 8 * lane);
    u64 xA = 0ull, xB = 0ull;
    fma2(xA, hA[0], a0); fma2(xA, hA[1], a1); fma2(xA, hA[2], b0); fma2(xA, hA[3], b1); fma2(xA, hA[4], c);
    fma2(xB, hB[0], a0); fma2(xB, hB[1], a1); fma2(xB, hB[2], b0); fma2(xB, hB[3], b1); fma2(xB, hB[4], c);
    float2 fA = un2(xA), fB = un2(xB);
    float2 r2 = wsum2(fA.x + fA.y, fB.x + fB.y);
    sA = r2.x; sB = r2.y;
}

__device__ __forceinline__ float dot1(unsigned r, const u64* h, int lane) {
    u64 a0, a1, b0, b1, c;
    lds128(a0, a1, r + 16 * lane);
    lds128(b0, b1, r + 512 + 16 * lane);
    c = lds64(r + 1024 + 8 * lane);
    u64 x = 0ull;
    fma2(x, h[0], a0); fma2(x, h[1], a1); fma2(x, h[2], b0); fma2(x, h[3], b1); fma2(x, h[4], c);
    float2 f = un2(x);
    return wsum1(f.x + f.y);
}

__device__ __forceinline__ void acc2(unsigned r, u64 pA, u64 pB, u64* zA, u64* zB, int lane) {
    u64 a0, a1, b0, b1, c;
    lds128(a0, a1, r + 16 * lane);
    lds128(b0, b1, r + 512 + 16 * lane);
    c = lds64(r + 1024 + 8 * lane);
    fma2(zA[0], pA, a0); fma2(zA[1], pA, a1); fma2(zA[2], pA, b0); fma2(zA[3], pA, b1); fma2(zA[4], pA, c);
    fma2(zB[0], pB, a0); fma2(zB[1], pB, a1); fma2(zB[2], pB, b0); fma2(zB[3], pB, b1); fma2(zB[4], pB, c);
}

__device__ __forceinline__ void acc1(unsigned r, u64 p, u64* z, int lane) {
    u64 a0, a1, b0, b1, c;
    lds128(a0, a1, r + 16 * lane);
    lds128(b0, b1, r + 512 + 16 * lane);
    c = lds64(r + 1024 + 8 * lane);
    fma2(z[0], p, a0); fma2(z[1], p, a1); fma2(z[2], p, b0); fma2(z[3], p, b1); fma2(z[4], p, c);
}

// ---------------------------------------------------------------------------
// Precompute: proj_j = (c_j @ W)/tau, const_j = (b.c_j)/tau. 10 codes/block.
// Software-pipelined: prefetch next 8 W rows while computing current 8.
// Code values fetched via LDS.128.
// ---------------------------------------------------------------------------
__global__ __launch_bounds__(320) void proj_kernel(
    const float* __restrict__ catc, const float* __restrict__ typc,
    const float* __restrict__ varc, const float* __restrict__ spac,
    const float* __restrict__ Wc, const float* __restrict__ bc,
    const float* __restrict__ Wt, const float* __restrict__ bt,
    const float* __restrict__ Wv, const float* __restrict__ bv,
    const float* __restrict__ Ws, const float* __restrict__ bs,
    const float* __restrict__ log_tau)
{
    __shared__ float csm[10 * D];
    __shared__ float red[320];
    int j0 = blockIdx.x * 10;
    const float *W, *b, *src;
    if (j0 < TYPE_BASE)      { W = Wc; b = bc; src = catc + j0 * D; }
    else if (j0 < VAR_BASE)  { W = Wt; b = bt; src = typc + (j0 - TYPE_BASE) * D; }
    else if (j0 < SPAT_BASE) { W = Wv; b = bv; src = varc + (j0 - VAR_BASE) * D; }
    else                     { W = Ws; b = bs; src = spac + (j0 - SPAT_BASE) * D; }
    int k = threadIdx.x;
    for (int i = k; i < 10 * D; i += 320) csm[i] = src[i];
    __syncthreads();

    float tau = fminf(fmaxf(expf(log_tau[0]) + 0.1f, 0.1f), 2.0f);
    float it = 1.0f / tau;

    unsigned cbase = s2u(csm);
    u64 acc[10];
    #pragma unroll
    for (int j = 0; j < 10; j++) acc[j] = 0ull;

    float wa[8], wb[8];
    #pragma unroll
    for (int u = 0; u < 8; u++) wa[u] = W[u * D + k];

    for (int d0 = 0; d0 < D; d0 += 16) {
        // prefetch chunk B (d0+8) — always in range (d0 <= 304 -> d0+15 <= 319)
        #pragma unroll
        for (int u = 0; u < 8; u++) wb[u] = W[(d0 + 8 + u) * D + k];
        // compute chunk A (d0)
        {
            u64 wp0 = pk2(wa[0], wa[1]), wp1 = pk2(wa[2], wa[3]);
            u64 wp2 = pk2(wa[4], wa[5]), wp3 = pk2(wa[6], wa[7]);
            #pragma unroll
            for (int j = 0; j < 10; j++) {
                u64 c0, c1, c2, c3;
                lds128(c0, c1, cbase + (j * D + d0) * 4);
                lds128(c2, c3, cbase + (j * D + d0 + 4) * 4);
                fma2(acc[j], c0, wp0); fma2(acc[j], c1, wp1);
                fma2(acc[j], c2, wp2); fma2(acc[j], c3, wp3);
            }
        }
        // prefetch chunk A for next iter (guard last)
        int dn = (d0 + 16 < D) ? (d0 + 16) : 0;
        #pragma unroll
        for (int u = 0; u < 8; u++) wa[u] = W[(dn + u) * D + k];
        // compute chunk B (d0+8)
        {
            u64 wp0 = pk2(wb[0], wb[1]), wp1 = pk2(wb[2], wb[3]);
            u64 wp2 = pk2(wb[4], wb[5]), wp3 = pk2(wb[6], wb[7]);
            #pragma unroll
            for (int j = 0; j < 10; j++) {
                u64 c0, c1, c2, c3;
                lds128(c0, c1, cbase + (j * D + d0 + 8) * 4);
                lds128(c2, c3, cbase + (j * D + d0 + 12) * 4);
                fma2(acc[j], c0, wp0); fma2(acc[j], c1, wp1);
                fma2(acc[j], c2, wp2); fma2(acc[j], c3, wp3);
            }
        }
    }
    #pragma unroll
    for (int j = 0; j < 10; j++) {
        float2 f = un2(acc[j]);
        g_proj[(j0 + j) * D + k] = (f.x + f.y) * it;
    }

    for (int j = 0; j < 10; j++) {
        red[k] = b[k] * csm[j * D + k];
        __syncthreads();
        if (k < 160) red[k] += red[k + 160]; __syncthreads();
        if (k < 80)  red[k] += red[k + 80];  __syncthreads();
        if (k < 40)  red[k] += red[k + 40];  __syncthreads();
        if (k < 20)  red[k] += red[k + 20];  __syncthreads();
        if (k < 10)  red[k] += red[k + 10];  __syncthreads();
        if (k < 5)   red[k] += red[k + 5];   __syncthreads();
        if (k == 0) g_const[j0 + j] = (red[0] + red[1] + red[2] + red[3] + red[4]) * it;
        __syncthreads();
    }
}

// ---------------------------------------------------------------------------
// Phase A: category + spatial. 2 tokens per warp iteration, h-prefetch
// pipelining, 2 blocks/SM (256 thr, 102.5KB smem each).
// ---------------------------------------------------------------------------
#define TPB_A 256
#define GRID_A 296
#define SMEM_A ((80 * D + 40) * 4)
__global__ __launch_bounds__(TPB_A, 2) void phaseA_kernel(
    const float* __restrict__ x, const float* __restrict__ cat_codes,
    const float* __restrict__ spat_codes, float* __restrict__ out)
{
    extern __shared__ float sm[];
    // [0) sCp, [20*D) sCo, [40*D) sSp, [60*D) sSo, [80*D) 40 consts
    for (int i = threadIdx.x; i < 20 * D; i += TPB_A) {
        sm[i]           = g_proj[i];
        sm[20 * D + i]  = cat_codes[i];
        sm[40 * D + i]  = g_proj[SPAT_BASE * D + i];
        sm[60 * D + i]  = spat_codes[i];
    }
    if (threadIdx.x < 20) {
        sm[80 * D + threadIdx.x]      = g_const[threadIdx.x];
        sm[80 * D + 20 + threadIdx.x] = g_const[SPAT_BASE + threadIdx.x];
    }
    __syncthreads();

    unsigned sb = s2u(sm);
    unsigned aCp = sb, aCo = sb + 20 * ROWB, aSp = sb + 40 * ROWB, aSo = sb + 60 * ROWB;
    const float* cc = sm + 80 * D;

    int lane = threadIdx.x & 31;
    int warp = threadIdx.x >> 5;
    int gw = blockIdx.x * (TPB_A / 32) + warp;
    int nw = GRID_A * (TPB_A / 32);

    u64 hA[5], hB[5], hnA[5], hnB[5];
    if (gw < NTOK / 2) {
        load_h(x + (size_t)(2 * gw) * D, hA, lane);
        load_h(x + (size_t)(2 * gw + 1) * D, hB, lane);
    }

    for (int p = gw; p < NTOK / 2; p += nw) {
        int tA = 2 * p, tB = 2 * p + 1;
        u64 zA[5] = {0,0,0,0,0}, zB[5] = {0,0,0,0,0};
        float simA[20], simB[20];

        // --- category dots ---
        #pragma unroll
        for (int j = 0; j < 20; j++) {
            dot2(aCp + j * ROWB, hA, hB, simA[j], simB[j], lane);
            simA[j] += cc[j]; simB[j] += cc[j];
        }
        float mA = simA[0]; int ciA = 0;
        float mB = simB[0]; int ciB = 0;
        #pragma unroll
        for (int j = 1; j < 20; j++) {
            if (simA[j] > mA) { mA = simA[j]; ciA = j; }
            if (simB[j] > mB) { mB = simB[j]; ciB = j; }
        }
        float sA = 0.f, sB = 0.f;
        #pragma unroll
        for (int j = 0; j < 20; j++) {
            simA[j] = __expf(simA[j] - mA); sA += simA[j];
            simB[j] = __expf(simB[j] - mB); sB += simB[j];
        }
        float iA = 1.f / sA, iB = 1.f / sB;
        #pragma unroll
        for (int j = 0; j < 20; j++) {
            float pA = simA[j] * iA, pB = simB[j] * iB;
            acc2(aCo + j * ROWB, pk2(pA, pA), pk2(pB, pB), zA, zB, lane);
        }
        if (lane == 0) { g_cat[tA] = ciA; g_cat[tB] = ciB; }

        // --- spatial dots (h last use) ---
        #pragma unroll
        for (int j = 0; j < 20; j++) {
            dot2(aSp + j * ROWB, hA, hB, simA[j], simB[j], lane);
            simA[j] += cc[20 + j]; simB[j] += cc[20 + j];
        }

        // prefetch next pair's h while the spatial softmax+acc runs
        int pn = p + nw;
        if (pn < NTOK / 2) {
            load_h(x + (size_t)(2 * pn) * D, hnA, lane);
            load_h(x + (size_t)(2 * pn + 1) * D, hnB, lane);
        }

        mA = simA[0]; mB = simB[0];
        #pragma unroll
        for (int j = 1; j < 20; j++) { mA = fmaxf(mA, simA[j]); mB = fmaxf(mB, simB[j]); }
        sA = 0.f; sB = 0.f;
        #pragma unroll
        for (int j = 0; j < 20; j++) {
            simA[j] = __expf(simA[j] - mA); sA += simA[j];
            simB[j] = __expf(simB[j] - mB); sB += simB[j];
        }
        iA = 1.f / sA; iB = 1.f / sB;
        #pragma unroll
        for (int j = 0; j < 20; j++) {
            float pA = simA[j] * iA, pB = simB[j] * iB;
            acc2(aSo + j * ROWB, pk2(pA, pA), pk2(pB, pB), zA, zB, lane);
        }

        float* oA = out + (size_t)tA * D;
        float* oB = out + (size_t)tB * D;
        ulonglong2 v;
        v.x = zA[0]; v.y = zA[1]; ((ulonglong2*)oA)[lane] = v;
        v.x = zA[2]; v.y = zA[3]; ((ulonglong2*)oA)[32 + lane] = v;
        ((u64*)oA)[128 + lane] = zA[4];
        v.x = zB[0]; v.y = zB[1]; ((ulonglong2*)oB)[lane] = v;
        v.x = zB[2]; v.y = zB[3]; ((ulonglong2*)oB)[32 + lane] = v;
        ((u64*)oB)[128 + lane] = zB[4];

        #pragma unroll
        for (int i = 0; i < 5; i++) { hA[i] = hnA[i]; hB[i] = hnB[i]; }
    }
}

// ---------------------------------------------------------------------------
// Phase B: type + variant. 7 blocks/category; tokens paired via carried pend.
// ---------------------------------------------------------------------------
#define NB_PER_CAT 7
#define TPB_B 512
#define SMEM_B ((100 * D + 50) * 4)

__device__ __forceinline__ void processB(
    int tA, int tB, const float* __restrict__ x, float* __restrict__ out,
    unsigned aTp, unsigned aTo, unsigned aVp, unsigned aVo,
    const float* tc, const float* vc, int lane)
{
    u64 hA[5], hB[5];
    load_h(x + (size_t)tA * D, hA, lane);
    load_h(x + (size_t)tB * D, hB, lane);
    u64 zA[5] = {0,0,0,0,0}, zB[5] = {0,0,0,0,0};

    float simA[10], simB[10];
    #pragma unroll
    for (int k = 0; k < 10; k++) {
        dot2(aTp + k * ROWB, hA, hB, simA[k], simB[k], lane);
        simA[k] += tc[k]; simB[k] += tc[k];
    }
    float mA = simA[0]; int ltA = 0;
    float mB = simB[0]; int ltB = 0;
    #pragma unroll
    for (int k = 1; k < 10; k++) {
        if (simA[k] > mA) { mA = simA[k]; ltA = k; }
        if (simB[k] > mB) { mB = simB[k]; ltB = k; }
    }
    float sA = 0.f, sB = 0.f;
    #pragma unroll
    for (int k = 0; k < 10; k++) {
        simA[k] = __expf(simA[k] - mA); sA += simA[k];
        simB[k] = __expf(simB[k] - mB); sB += simB[k];
    }
    float iA = 1.f / sA, iB = 1.f / sB;
    #pragma unroll
    for (int k = 0; k < 10; k++) {
        float pA = simA[k] * iA, pB = simB[k] * iB;
        acc2(aTo + k * ROWB, pk2(pA, pA), pk2(pB, pB), zA, zB, lane);
    }

    // variant: selected-type rows differ per token
    {
        int vb = ltA * 4;
        float sv[4];
        #pragma unroll
        for (int v = 0; v < 4; v++) sv[v] = dot1(aVp + (vb + v) * ROWB, hA, lane) + vc[vb + v];
        float mv = fmaxf(fmaxf(sv[0], sv[1]), fmaxf(sv[2], sv[3]));
        float s = 0.f;
        #pragma unroll
        for (int v = 0; v < 4; v++) { sv[v] = __expf(sv[v] - mv); s += sv[v]; }
        float inv = 1.f / s;
        #pragma unroll
        for (int v = 0; v < 4; v++) { float pp = sv[v] * inv; acc1(aVo + (vb + v) * ROWB, pk2(pp, pp), zA, lane); }
    }
    {
        int vb = ltB * 4;
        float sv[4];
        #pragma unroll
        for (int v = 0; v < 4; v++) sv[v] = dot1(aVp + (vb + v) * ROWB, hB, lane) + vc[vb + v];
        float mv = fmaxf(fmaxf(sv[0], sv[1]), fmaxf(sv[2], sv[3]));
        float s = 0.f;
        #pragma unroll
        for (int v = 0; v < 4; v++) { sv[v] = __expf(sv[v] - mv); s += sv[v]; }
        float inv = 1.f / s;
        #pragma unroll
        for (int v = 0; v < 4; v++) { float pp = sv[v] * inv; acc1(aVo + (vb + v) * ROWB, pk2(pp, pp), zB, lane); }
    }

    // out += z (RMW)
    {
        float* o = out + (size_t)tA * D;
        ulonglong2* o2 = (ulonglong2*)o;
        ulonglong2 v = o2[lane];
        v.x = add2(v.x, zA[0]); v.y = add2(v.y, zA[1]); o2[lane] = v;
        v = o2[32 + lane];
        v.x = add2(v.x, zA[2]); v.y = add2(v.y, zA[3]); o2[32 + lane] = v;
        ((u64*)o)[128 + lane] = add2(((u64*)o)[128 + lane], zA[4]);
    }
    if (tB != tA) {
        float* o = out + (size_t)tB * D;
        ulonglong2* o2 = (ulonglong2*)o;
        ulonglong2 v = o2[lane];
        v.x = add2(v.x, zB[0]); v.y = add2(v.y, zB[1]); o2[lane] = v;
        v = o2[32 + lane];
        v.x = add2(v.x, zB[2]); v.y = add2(v.y, zB[3]); o2[32 + lane] = v;
        ((u64*)o)[128 + lane] = add2(((u64*)o)[128 + lane], zB[4]);
    }
}

__global__ __launch_bounds__(TPB_B, 1) void phaseB_kernel(
    const float* __restrict__ x, const float* __restrict__ type_codes,
    const float* __restrict__ var_codes, float* __restrict__ out)
{
    extern __shared__ float sm[];
    // [0) sTp(10), [10*D) sTo(10), [20*D) sVp(40), [60*D) sVo(40), [100*D) 50 consts
    int c = blockIdx.x / NB_PER_CAT;
    int b = blockIdx.x % NB_PER_CAT;

    for (int i = threadIdx.x; i < 10 * D; i += TPB_B) {
        sm[i]          = g_proj[(TYPE_BASE + c * 10) * D + i];
        sm[10 * D + i] = type_codes[(size_t)c * 10 * D + i];
    }
    for (int i = threadIdx.x; i < 40 * D; i += TPB_B) {
        sm[20 * D + i] = g_proj[(VAR_BASE + c * 40) * D + i];
        sm[60 * D + i] = var_codes[(size_t)c * 40 * D + i];
    }
    if (threadIdx.x < 10) sm[100 * D + threadIdx.x] = g_const[TYPE_BASE + c * 10 + threadIdx.x];
    if (threadIdx.x < 40) sm[100 * D + 10 + threadIdx.x] = g_const[VAR_BASE + c * 40 + threadIdx.x];
    __syncthreads();

    unsigned sb = s2u(sm);
    unsigned aTp = sb, aTo = sb + 10 * ROWB, aVp = sb + 20 * ROWB, aVo = sb + 60 * ROWB;
    const float* tc = sm + 100 * D;
    const float* vc = sm + 100 * D + 10;

    int lane = threadIdx.x & 31;
    int warp = threadIdx.x >> 5;
    const int NW = NB_PER_CAT * (TPB_B / 32);            // 112 warps per category
    int gwc = b * (TPB_B / 32) + warp;
    int chunk = (((NTOK + NW - 1) / NW) + 31) & ~31;     // 32-aligned
    int t0 = gwc * chunk;
    int t1 = min(t0 + chunk, NTOK);

    int pend = -1;
    for (int tb = t0; tb < t1; tb += 32) {
        int t = tb + lane;
        int myc = (t < t1) ? g_cat[t] : -1;
        unsigned mask = __ballot_sync(0xffffffffu, myc == c);
        while (mask) {
            int bit = __ffs(mask) - 1;
            mask &= mask - 1;
            int tok = tb + bit;
            if (pend < 0) pend = tok;
            else {
                processB(pend, tok, x, out, aTp, aTo, aVp, aVo, tc, vc, lane);
                pend = -1;
            }
        }
    }
    if (pend >= 0)
        processB(pend, pend, x, out, aTp, aTo, aVp, aVo, tc, vc, lane);
}

// ---------------------------------------------------------------------------
extern "C" void kernel_launch(void* const* d_in, const int* in_sizes, int n_in,
                              void* d_out, int out_size) {
    const float* x    = (const float*)d_in[0];
    const float* catc = (const float*)d_in[1];
    const float* typc = (const float*)d_in[2];
    const float* varc = (const float*)d_in[3];
    const float* spac = (const float*)d_in[4];
    const float* ltau = (const float*)d_in[5];
    const float* Wc   = (const float*)d_in[6];
    const float* bc   = (const float*)d_in[7];
    const float* Wt   = (const float*)d_in[8];
    const float* bt   = (const float*)d_in[9];
    const float* Wv   = (const float*)d_in[10];
    const float* bv   = (const float*)d_in[11];
    const float* Ws   = (const float*)d_in[12];
    const float* bs   = (const float*)d_in[13];
    float* out = (float*)d_out;

    cudaFuncSetAttribute(phaseA_kernel, cudaFuncAttributeMaxDynamicSharedMemorySize, SMEM_A);
    cudaFuncSetAttribute(phaseB_kernel, cudaFuncAttributeMaxDynamicSharedMemorySize, SMEM_B);

    proj_kernel<<<NPROJ / 10, 320>>>(catc, typc, varc, spac,
                                     Wc, bc, Wt, bt, Wv, bv, Ws, bs, ltau);
    phaseA_kernel<<<GRID_A, TPB_A, SMEM_A>>>(x, catc, spac, out);
    phaseB_kernel<<<NCAT * NB_PER_CAT, TPB_B, SMEM_B>>>(x, typc, varc, out);
}